// round 1
// baseline (speedup 1.0000x reference)
#include <cuda_runtime.h>

// ChannelPruner: out[b,o,h,w] = sum_c W[o,c] * x[b,c,h,w]
// Strategy: W is tiny (256x256). Kernel 1 compacts each row of W to its
// nonzero (col, val) pairs in device-global scratch. Kernel 2 streams x
// as float4, computing each output element as a short sparse dot product.
// For the given data (pruned identity) this is a bandwidth-bound
// copy/zero: ~180 MB of HBM traffic.

#define N_CH   256
#define HW     3136              // 56*56
#define HW4    (HW / 4)          // 784 float4 per channel-plane
#define BATCH  32

__device__ int   g_nnz[N_CH];
__device__ int   g_col[N_CH * N_CH];
__device__ float g_val[N_CH * N_CH];

// --- Kernel 1: compact W rows (one thread per output channel) ---
__global__ void compact_rows_kernel(const float* __restrict__ w) {
    int o = blockIdx.x * blockDim.x + threadIdx.x;
    if (o >= N_CH) return;
    int n = 0;
    const float* row = w + (long)o * N_CH;
    int*   cols = g_col + o * N_CH;
    float* vals = g_val + o * N_CH;
    #pragma unroll 4
    for (int c = 0; c < N_CH; ++c) {
        float v = row[c];
        if (v != 0.0f) {
            cols[n] = c;
            vals[n] = v;
            ++n;
        }
    }
    g_nnz[o] = n;
}

// --- Kernel 2: streaming sparse-dot over pixels (float4) ---
// One thread per output float4. Layout: ((b*256 + o)*784 + p4).
__global__ void __launch_bounds__(256)
prune_stream_kernel(const float* __restrict__ x, float* __restrict__ out) {
    long idx = (long)blockIdx.x * blockDim.x + threadIdx.x;
    const long total = (long)BATCH * N_CH * HW4;
    if (idx >= total) return;

    int p4  = (int)(idx % HW4);
    long bo = idx / HW4;           // b*256 + o
    int o   = (int)(bo % N_CH);
    long b  = bo / N_CH;

    int n = g_nnz[o];
    float4 acc = make_float4(0.f, 0.f, 0.f, 0.f);

    const float4* x4 = (const float4*)x;
    const int*   cols = g_col + o * N_CH;
    const float* vals = g_val + o * N_CH;

    for (int j = 0; j < n; ++j) {
        int   c = cols[j];
        float v = vals[j];
        float4 xv = x4[(b * N_CH + c) * HW4 + p4];
        acc.x = fmaf(v, xv.x, acc.x);
        acc.y = fmaf(v, xv.y, acc.y);
        acc.z = fmaf(v, xv.z, acc.z);
        acc.w = fmaf(v, xv.w, acc.w);
    }

    ((float4*)out)[idx] = acc;
}

extern "C" void kernel_launch(void* const* d_in, const int* in_sizes, int n_in,
                              void* d_out, int out_size) {
    const float* x = (const float*)d_in[0];          // (32,256,56,56) fp32
    const float* w = (const float*)d_in[1];          // (256,256,1,1)  fp32
    float* out = (float*)d_out;

    compact_rows_kernel<<<1, 256>>>(w);

    const long total = (long)BATCH * N_CH * HW4;     // 6,422,528 float4
    int threads = 256;
    long blocks = (total + threads - 1) / threads;   // 25,088 blocks
    prune_stream_kernel<<<(unsigned)blocks, threads>>>(x, out);
}

// round 2
// speedup vs baseline: 1.7692x; 1.7692x over previous
#include <cuda_runtime.h>

// ChannelPruner: out[b,o,h,w] = sum_c W[o,c] * x[b,c,h,w]
// Fused single kernel: each block owns one (b, o) plane of 784 float4.
// Warp 0 compacts W row o (ballot+popc scan) into smem; all 256 threads
// then stream the plane as a short sparse dot product. For the pruned
// identity this is a bandwidth-bound copy/zero (~180 MB HBM traffic).

#define N_CH   256
#define HW4    784               // 56*56/4 float4 per channel-plane
#define BATCH  32

__global__ void __launch_bounds__(256)
fused_prune_kernel(const float* __restrict__ x,
                   const float* __restrict__ w,
                   float* __restrict__ out) {
    __shared__ int   s_col[N_CH];
    __shared__ float s_val[N_CH];
    __shared__ int   s_nnz;

    const int o   = blockIdx.x;          // output channel
    const int b   = blockIdx.y;          // batch
    const int tid = threadIdx.x;

    // --- warp 0: compact row o of W into (col, val) pairs ---
    if (tid < 32) {
        const float* row = w + o * N_CH;
        int off = 0;
        #pragma unroll
        for (int ch = 0; ch < N_CH / 32; ++ch) {
            float v = row[ch * 32 + tid];
            unsigned m = __ballot_sync(0xffffffffu, v != 0.0f);
            int pre = __popc(m & ((1u << tid) - 1u));
            if (v != 0.0f) {
                s_col[off + pre] = ch * 32 + tid;
                s_val[off + pre] = v;
            }
            off += __popc(m);
        }
        if (tid == 0) s_nnz = off;
    }
    __syncthreads();

    const int n = s_nnz;

    // base pointers for this (b, o)
    const float4* xb = (const float4*)x + (b * N_CH) * HW4;
    float4*       ob = (float4*)out + (b * N_CH + o) * HW4;

    // stream the plane: 784 float4, 256 threads -> 3-4 iters/thread
    for (int p = tid; p < HW4; p += 256) {
        float4 acc = make_float4(0.f, 0.f, 0.f, 0.f);
        for (int j = 0; j < n; ++j) {
            float  v  = s_val[j];
            float4 xv = __ldcs(&xb[s_col[j] * HW4 + p]);
            acc.x = fmaf(v, xv.x, acc.x);
            acc.y = fmaf(v, xv.y, acc.y);
            acc.z = fmaf(v, xv.z, acc.z);
            acc.w = fmaf(v, xv.w, acc.w);
        }
        __stcs(&ob[p], acc);
    }
}

extern "C" void kernel_launch(void* const* d_in, const int* in_sizes, int n_in,
                              void* d_out, int out_size) {
    const float* x = (const float*)d_in[0];   // (32,256,56,56) fp32
    const float* w = (const float*)d_in[1];   // (256,256,1,1)  fp32
    float* out = (float*)d_out;

    dim3 grid(N_CH, BATCH);                   // 8192 blocks
    fused_prune_kernel<<<grid, 256>>>(x, w, out);
}